// round 9
// baseline (speedup 1.0000x reference)
#include <cuda_runtime.h>
#include <math.h>

#define N_ROWS 131072
#define D      2048
#define NT     256            // threads per block
#define CPT    8              // columns per thread = D / NT
#define NBLK   296            // persistent grid = 2 * 148 SMs
#define RB     4              // rows per batch
#define NBATCH (N_ROWS / RB)  // 32768
#define INV_T  10.0f          // 1 / temperature
#define EPS    1e-8f

// Scratch (device globals, zero-initialized at load; dsdm_out restores zero
// after each use so graph replays see identical initial state).
__device__ float g_stage[D];   // atomically accumulated unnormalized output
__device__ float g_L;          // atomically accumulated sum of weights

// ---------------------------------------------------------------------------
// Main persistent kernel (loop identical to the R6 winner): double-buffered
// loads, two barriers per batch, tid<RB transcendentals, fixed-max softmax.
// Tail: REDG-accumulate acc into g_stage (no g_pacc round-trip).
// ---------------------------------------------------------------------------
__global__ __launch_bounds__(NT) void dsdm_main(const float* __restrict__ A,
                                                const float* __restrict__ q) {
    __shared__ float s_dot[8][RB];
    __shared__ float s_sq[8][RB];
    __shared__ float s_w[RB];
    __shared__ float s_tmp[8];

    const int tid  = threadIdx.x;
    const int wid  = tid >> 5;
    const int lane = tid & 31;

    // --- q slice + ||q|| ---
    float qv[CPT];
    {
        const float4 q0 = reinterpret_cast<const float4*>(q)[tid * 2 + 0];
        const float4 q1 = reinterpret_cast<const float4*>(q)[tid * 2 + 1];
        qv[0] = q0.x; qv[1] = q0.y; qv[2] = q0.z; qv[3] = q0.w;
        qv[4] = q1.x; qv[5] = q1.y; qv[6] = q1.z; qv[7] = q1.w;
    }
    float qsq = 0.f;
    #pragma unroll
    for (int i = 0; i < CPT; i++) qsq += qv[i] * qv[i];
    #pragma unroll
    for (int o = 16; o; o >>= 1) qsq += __shfl_xor_sync(0xffffffffu, qsq, o);
    if (lane == 0) s_tmp[wid] = qsq;
    __syncthreads();
    if (tid == 0) {
        float s = 0.f;
        #pragma unroll
        for (int w = 0; w < 8; w++) s += s_tmp[w];
        s_tmp[0] = sqrtf(s);
    }
    __syncthreads();
    const float qn = s_tmp[0];
    __syncthreads();

    float acc[CPT];
    #pragma unroll
    for (int i = 0; i < CPT; i++) acc[i] = 0.f;
    float l = 0.f;

    // double-buffered row registers: RB rows x 2 float4 each
    float4 bA0[RB], bA1[RB], bB0[RB], bB1[RB];

#define LOAD_BATCH(v0, v1, batch)                                             \
    {                                                                         \
        _Pragma("unroll")                                                     \
        for (int r = 0; r < RB; r++) {                                        \
            const float4* rp = reinterpret_cast<const float4*>(               \
                A + ((size_t)(batch) * RB + r) * D) + tid * 2;                \
            v0[r] = rp[0];                                                    \
            v1[r] = rp[1];                                                    \
        }                                                                     \
    }

#define PROCESS(v0, v1)                                                       \
    {                                                                         \
        float dt[RB], sq[RB];                                                 \
        _Pragma("unroll")                                                     \
        for (int r = 0; r < RB; r++) {                                        \
            float d = v0[r].x * qv[0] + v0[r].y * qv[1] +                     \
                      v0[r].z * qv[2] + v0[r].w * qv[3] +                     \
                      v1[r].x * qv[4] + v1[r].y * qv[5] +                     \
                      v1[r].z * qv[6] + v1[r].w * qv[7];                      \
            float s = v0[r].x * v0[r].x + v0[r].y * v0[r].y +                 \
                      v0[r].z * v0[r].z + v0[r].w * v0[r].w +                 \
                      v1[r].x * v1[r].x + v1[r].y * v1[r].y +                 \
                      v1[r].z * v1[r].z + v1[r].w * v1[r].w;                  \
            dt[r] = d; sq[r] = s;                                             \
        }                                                                     \
        _Pragma("unroll")                                                     \
        for (int r = 0; r < RB; r++) {                                        \
            _Pragma("unroll")                                                 \
            for (int o = 16; o; o >>= 1) {                                    \
                dt[r] += __shfl_xor_sync(0xffffffffu, dt[r], o);              \
                sq[r] += __shfl_xor_sync(0xffffffffu, sq[r], o);              \
            }                                                                 \
        }                                                                     \
        if (lane == 0) {                                                      \
            _Pragma("unroll")                                                 \
            for (int r = 0; r < RB; r++) {                                    \
                s_dot[wid][r] = dt[r]; s_sq[wid][r] = sq[r];                  \
            }                                                                 \
        }                                                                     \
        __syncthreads();                                                      \
        if (tid < RB) {                                                       \
            float d = 0.f, s = 0.f;                                           \
            _Pragma("unroll")                                                 \
            for (int w = 0; w < 8; w++) { d += s_dot[w][tid]; s += s_sq[w][tid]; } \
            const float sim = d / fmaxf(sqrtf(s) * qn, EPS);                  \
            s_w[tid] = __expf((sim - 1.0f) * INV_T);                          \
        }                                                                     \
        __syncthreads();                                                      \
        _Pragma("unroll")                                                     \
        for (int r = 0; r < RB; r++) {                                        \
            const float w = s_w[r];                                           \
            l += w;                                                           \
            acc[0] += w * v0[r].x;                                            \
            acc[1] += w * v0[r].y;                                            \
            acc[2] += w * v0[r].z;                                            \
            acc[3] += w * v0[r].w;                                            \
            acc[4] += w * v1[r].x;                                            \
            acc[5] += w * v1[r].y;                                            \
            acc[6] += w * v1[r].z;                                            \
            acc[7] += w * v1[r].w;                                            \
        }                                                                     \
    }

    // --- grid-stride pipeline over batches, unrolled x2 for reg buffers ---
    int batch = blockIdx.x;
    bool valid = (batch < NBATCH);
    if (valid) LOAD_BATCH(bA0, bA1, batch);

    while (valid) {
        int nb = batch + NBLK;
        bool vnext = (nb < NBATCH);
        if (vnext) LOAD_BATCH(bB0, bB1, nb);   // prefetch flies over barriers
        PROCESS(bA0, bA1);
        batch = nb; valid = vnext;
        if (!valid) break;

        nb = batch + NBLK;
        vnext = (nb < NBATCH);
        if (vnext) LOAD_BATCH(bA0, bA1, nb);
        PROCESS(bB0, bB1);
        batch = nb; valid = vnext;
    }
#undef LOAD_BATCH
#undef PROCESS

    // --- publish: fire-and-forget REDG accumulation (no round-trip) ---
    if (tid == 0) atomicAdd(&g_L, l);
    float* sp = g_stage + tid * CPT;
    #pragma unroll
    for (int i = 0; i < CPT; i++) atomicAdd(sp + i, acc[i]);
}

// ---------------------------------------------------------------------------
// Finalize: ONE block. out = stage / L, then restore staging to zero so the
// next graph replay sees identical initial state.
// ---------------------------------------------------------------------------
__global__ __launch_bounds__(NT) void dsdm_out(float* __restrict__ out) {
    const int tid = threadIdx.x;
    const float invL = 1.0f / g_L;

    float v[D / NT];
    #pragma unroll
    for (int i = 0; i < D / NT; i++) v[i] = g_stage[i * NT + tid];
    #pragma unroll
    for (int i = 0; i < D / NT; i++) {
        out[i * NT + tid] = v[i] * invL;
        g_stage[i * NT + tid] = 0.f;
    }
    __syncthreads();               // all threads have read g_L
    if (tid == 0) g_L = 0.f;
}

extern "C" void kernel_launch(void* const* d_in, const int* in_sizes, int n_in,
                              void* d_out, int out_size) {
    const float* addresses = (const float*)d_in[0];   // [131072, 2048] f32
    const float* query     = (const float*)d_in[1];   // [2048] f32
    float* out = (float*)d_out;                       // [2048] f32

    dsdm_main<<<NBLK, NT>>>(addresses, query);
    dsdm_out<<<1, NT>>>(out);
}

// round 10
// speedup vs baseline: 1.1196x; 1.1196x over previous
#include <cuda_runtime.h>
#include <math.h>

#define N_ROWS 131072
#define D      2048
#define NT     256            // threads per block
#define CPT    8              // columns per thread = D / NT
#define NBLK   296            // persistent grid = 2 * 148 SMs
#define RB     4              // rows per batch
#define NBATCH (N_ROWS / RB)  // 32768
#define NBY    37             // b-chunks in finalize (296 = 8 * 37)
#define BCH    (NBLK / NBY)   // 8 partials per finalize block
#define INV_T  10.0f          // 1 / temperature
#define EPS    1e-8f

// Scratch (device globals: no allocations allowed)
__device__ float g_pacc[(size_t)NBLK * D];   // per-block partial weighted sums
__device__ float g_pl[NBLK];                 // per-block sum of exp((sim-1)*10)

// ---------------------------------------------------------------------------
// Main persistent kernel (UNCHANGED from R6 winner, 157.7us config):
// double-buffered loads, two barriers/batch, tid<RB transcendentals,
// fixed-max softmax, g_pacc/g_pl publish, blocks 0-7 zero the output.
// ---------------------------------------------------------------------------
__global__ __launch_bounds__(NT) void dsdm_main(const float* __restrict__ A,
                                                const float* __restrict__ q,
                                                float* __restrict__ out) {
    __shared__ float s_dot[8][RB];
    __shared__ float s_sq[8][RB];
    __shared__ float s_w[RB];
    __shared__ float s_tmp[8];

    const int tid  = threadIdx.x;
    const int wid  = tid >> 5;
    const int lane = tid & 31;

    // Zero the output (harness poisons it; dsdm_out accumulates atomically).
    if (blockIdx.x < D / NT) out[blockIdx.x * NT + tid] = 0.f;

    // --- q slice + ||q|| ---
    float qv[CPT];
    {
        const float4 q0 = reinterpret_cast<const float4*>(q)[tid * 2 + 0];
        const float4 q1 = reinterpret_cast<const float4*>(q)[tid * 2 + 1];
        qv[0] = q0.x; qv[1] = q0.y; qv[2] = q0.z; qv[3] = q0.w;
        qv[4] = q1.x; qv[5] = q1.y; qv[6] = q1.z; qv[7] = q1.w;
    }
    float qsq = 0.f;
    #pragma unroll
    for (int i = 0; i < CPT; i++) qsq += qv[i] * qv[i];
    #pragma unroll
    for (int o = 16; o; o >>= 1) qsq += __shfl_xor_sync(0xffffffffu, qsq, o);
    if (lane == 0) s_tmp[wid] = qsq;
    __syncthreads();
    if (tid == 0) {
        float s = 0.f;
        #pragma unroll
        for (int w = 0; w < 8; w++) s += s_tmp[w];
        s_tmp[0] = sqrtf(s);
    }
    __syncthreads();
    const float qn = s_tmp[0];
    __syncthreads();

    float acc[CPT];
    #pragma unroll
    for (int i = 0; i < CPT; i++) acc[i] = 0.f;
    float l = 0.f;

    // double-buffered row registers: RB rows x 2 float4 each
    float4 bA0[RB], bA1[RB], bB0[RB], bB1[RB];

#define LOAD_BATCH(v0, v1, batch)                                             \
    {                                                                         \
        _Pragma("unroll")                                                     \
        for (int r = 0; r < RB; r++) {                                        \
            const float4* rp = reinterpret_cast<const float4*>(               \
                A + ((size_t)(batch) * RB + r) * D) + tid * 2;                \
            v0[r] = rp[0];                                                    \
            v1[r] = rp[1];                                                    \
        }                                                                     \
    }

#define PROCESS(v0, v1)                                                       \
    {                                                                         \
        float dt[RB], sq[RB];                                                 \
        _Pragma("unroll")                                                     \
        for (int r = 0; r < RB; r++) {                                        \
            float d = v0[r].x * qv[0] + v0[r].y * qv[1] +                     \
                      v0[r].z * qv[2] + v0[r].w * qv[3] +                     \
                      v1[r].x * qv[4] + v1[r].y * qv[5] +                     \
                      v1[r].z * qv[6] + v1[r].w * qv[7];                      \
            float s = v0[r].x * v0[r].x + v0[r].y * v0[r].y +                 \
                      v0[r].z * v0[r].z + v0[r].w * v0[r].w +                 \
                      v1[r].x * v1[r].x + v1[r].y * v1[r].y +                 \
                      v1[r].z * v1[r].z + v1[r].w * v1[r].w;                  \
            dt[r] = d; sq[r] = s;                                             \
        }                                                                     \
        _Pragma("unroll")                                                     \
        for (int r = 0; r < RB; r++) {                                        \
            _Pragma("unroll")                                                 \
            for (int o = 16; o; o >>= 1) {                                    \
                dt[r] += __shfl_xor_sync(0xffffffffu, dt[r], o);              \
                sq[r] += __shfl_xor_sync(0xffffffffu, sq[r], o);              \
            }                                                                 \
        }                                                                     \
        if (lane == 0) {                                                      \
            _Pragma("unroll")                                                 \
            for (int r = 0; r < RB; r++) {                                    \
                s_dot[wid][r] = dt[r]; s_sq[wid][r] = sq[r];                  \
            }                                                                 \
        }                                                                     \
        __syncthreads();                                                      \
        if (tid < RB) {                                                       \
            float d = 0.f, s = 0.f;                                           \
            _Pragma("unroll")                                                 \
            for (int w = 0; w < 8; w++) { d += s_dot[w][tid]; s += s_sq[w][tid]; } \
            const float sim = d / fmaxf(sqrtf(s) * qn, EPS);                  \
            s_w[tid] = __expf((sim - 1.0f) * INV_T);                          \
        }                                                                     \
        __syncthreads();                                                      \
        _Pragma("unroll")                                                     \
        for (int r = 0; r < RB; r++) {                                        \
            const float w = s_w[r];                                           \
            l += w;                                                           \
            acc[0] += w * v0[r].x;                                            \
            acc[1] += w * v0[r].y;                                            \
            acc[2] += w * v0[r].z;                                            \
            acc[3] += w * v0[r].w;                                            \
            acc[4] += w * v1[r].x;                                            \
            acc[5] += w * v1[r].y;                                            \
            acc[6] += w * v1[r].z;                                            \
            acc[7] += w * v1[r].w;                                            \
        }                                                                     \
    }

    // --- grid-stride pipeline over batches, unrolled x2 for reg buffers ---
    int batch = blockIdx.x;
    bool valid = (batch < NBATCH);
    if (valid) LOAD_BATCH(bA0, bA1, batch);

    while (valid) {
        int nb = batch + NBLK;
        bool vnext = (nb < NBATCH);
        if (vnext) LOAD_BATCH(bB0, bB1, nb);   // prefetch flies over barriers
        PROCESS(bA0, bA1);
        batch = nb; valid = vnext;
        if (!valid) break;

        nb = batch + NBLK;
        vnext = (nb < NBATCH);
        if (vnext) LOAD_BATCH(bA0, bA1, nb);
        PROCESS(bB0, bB1);
        batch = nb; valid = vnext;
    }

    if (tid == 0) g_pl[blockIdx.x] = l;
    float4* pa = reinterpret_cast<float4*>(g_pacc + (size_t)blockIdx.x * D) + tid * 2;
    pa[0] = make_float4(acc[0], acc[1], acc[2], acc[3]);
    pa[1] = make_float4(acc[4], acc[5], acc[6], acc[7]);
#undef LOAD_BATCH
#undef PROCESS
}

// ---------------------------------------------------------------------------
// Finalize: grid (D/NT, NBY) = (8, 37). Partial loads issued FIRST (overlap
// the L reduction); cooperative 256-thread L reduction with shuffles and a
// single barrier (each warp redundantly folds the 8 per-warp sums -> no
// broadcast barrier); one atomicAdd per thread.
// ---------------------------------------------------------------------------
__global__ __launch_bounds__(NT) void dsdm_out(float* __restrict__ out) {
    __shared__ float s_tmp[8];
    const int tid  = threadIdx.x;
    const int wid  = tid >> 5;
    const int lane = tid & 31;

    // Issue the 8 independent partial loads first (longest latency, L2-hot).
    const int col = blockIdx.x * NT + tid;
    const int b0  = blockIdx.y * BCH;
    float v[BCH];
    #pragma unroll
    for (int j = 0; j < BCH; j++) {
        v[j] = g_pacc[(size_t)(b0 + j) * D + col];
    }

    // Cooperative L = sum of 296 per-block partials: each thread <=2 loads,
    // warp shuffle reduce, one barrier, per-warp redundant final fold.
    float lloc = g_pl[tid];
    if (tid < NBLK - NT) lloc += g_pl[NT + tid];
    #pragma unroll
    for (int o = 16; o; o >>= 1) lloc += __shfl_xor_sync(0xffffffffu, lloc, o);
    if (lane == 0) s_tmp[wid] = lloc;
    __syncthreads();
    float x = s_tmp[lane & 7];
    #pragma unroll
    for (int o = 4; o; o >>= 1) x += __shfl_xor_sync(0xffffffffu, x, o);
    const float invL = 1.0f / x;

    float s = 0.f;
    #pragma unroll
    for (int j = 0; j < BCH; j++) s += v[j];
    atomicAdd(&out[col], s * invL);
}

extern "C" void kernel_launch(void* const* d_in, const int* in_sizes, int n_in,
                              void* d_out, int out_size) {
    const float* addresses = (const float*)d_in[0];   // [131072, 2048] f32
    const float* query     = (const float*)d_in[1];   // [2048] f32
    float* out = (float*)d_out;                       // [2048] f32

    dsdm_main<<<NBLK, NT>>>(addresses, query, out);
    dsdm_out<<<dim3(D / NT, NBY), NT>>>(out);
}